// round 1
// baseline (speedup 1.0000x reference)
#include <cuda_runtime.h>
#include <math.h>

// ---------------------------------------------------------------------------
// Problem constants
// ---------------------------------------------------------------------------
#define B_   4
#define S_   2048
#define H_   1024
#define NH_  16
#define HD_  64
#define E_   4096
#define M_   (B_ * S_)          // 8192 tokens
#define QKV_N (3 * H_)          // 3072

// ---------------------------------------------------------------------------
// Scratch (device globals — no allocation allowed)
// ---------------------------------------------------------------------------
__device__ float g_h  [M_ * H_];     // ln1 output
__device__ float g_qkv[M_ * QKV_N];  // qkv projection
__device__ float g_o  [M_ * H_];     // attention output (B,S,C)
__device__ float g_x2 [M_ * H_];     // x + attn@Wo + bo
__device__ float g_h2 [M_ * H_];     // ln2 output
__device__ float g_a  [M_ * E_];     // gelu(fc1)

// ---------------------------------------------------------------------------
// LayerNorm: one block per row of 1024
// ---------------------------------------------------------------------------
__global__ __launch_bounds__(256) void ln_kernel(
    const float* __restrict__ x, const float* __restrict__ w,
    const float* __restrict__ b, float* __restrict__ out)
{
    const int row = blockIdx.x;
    const int tid = threadIdx.x;
    const float* xr = x + (size_t)row * H_;

    float v[4];
    float s = 0.f, s2 = 0.f;
#pragma unroll
    for (int i = 0; i < 4; i++) {
        v[i] = xr[tid + 256 * i];
        s += v[i];
        s2 += v[i] * v[i];
    }
    // warp reduce
#pragma unroll
    for (int off = 16; off > 0; off >>= 1) {
        s  += __shfl_xor_sync(0xffffffffu, s,  off);
        s2 += __shfl_xor_sync(0xffffffffu, s2, off);
    }
    __shared__ float red[8], red2[8];
    const int wid = tid >> 5, lane = tid & 31;
    if (lane == 0) { red[wid] = s; red2[wid] = s2; }
    __syncthreads();
    if (tid < 32) {
        float a = (tid < 8) ? red[tid]  : 0.f;
        float c = (tid < 8) ? red2[tid] : 0.f;
#pragma unroll
        for (int off = 4; off > 0; off >>= 1) {
            a += __shfl_xor_sync(0xffffffffu, a, off);
            c += __shfl_xor_sync(0xffffffffu, c, off);
        }
        if (tid == 0) { red[0] = a; red2[0] = c; }
    }
    __syncthreads();
    const float mu  = red[0] * (1.f / H_);
    const float var = red2[0] * (1.f / H_) - mu * mu;
    const float rstd = rsqrtf(var + 1e-5f);

    float* orow = out + (size_t)row * H_;
#pragma unroll
    for (int i = 0; i < 4; i++) {
        const int c = tid + 256 * i;
        orow[c] = (v[i] - mu) * rstd * w[c] + b[c];
    }
}

// ---------------------------------------------------------------------------
// GEMM: C[M,N] = A[M,K] @ B[K,N] + bias (+residual / gelu per mode)
// mode 0: bias only; mode 1: bias + residual; mode 2: bias + exact GELU
// 128x128 tile, 16 K-slab, 256 threads, 8x8 per thread, register prefetch.
// All dims assumed multiples of tile sizes (true for this problem).
// ---------------------------------------------------------------------------
__global__ __launch_bounds__(256) void gemm_kernel(
    const float* __restrict__ A, const float* __restrict__ B,
    const float* __restrict__ bias, const float* __restrict__ R,
    float* __restrict__ C, int M, int N, int K, int mode)
{
    __shared__ float As[16][128];
    __shared__ float Bs[16][128];

    const int tid  = threadIdx.x;
    const int brow = blockIdx.y * 128;
    const int bcol = blockIdx.x * 128;
    const int tr = (tid >> 4) * 8;
    const int tc = (tid & 15) * 8;

    // loader assignments
    const int a_row = tid >> 1;          // 0..127
    const int a_col = (tid & 1) * 8;     // 0 or 8
    const int b_row = tid >> 5;          // 0..7
    const int b_col = (tid & 31) * 4;    // 0..124

    const float* Aptr = A + (size_t)(brow + a_row) * K + a_col;
    const float* Bptr = B + (size_t)b_row * N + bcol + b_col;

    float acc[8][8];
#pragma unroll
    for (int i = 0; i < 8; i++)
#pragma unroll
        for (int j = 0; j < 8; j++) acc[i][j] = 0.f;

    float4 ra0, ra1, rb0, rb1;
    // initial tile load
    ra0 = *(const float4*)(Aptr);
    ra1 = *(const float4*)(Aptr + 4);
    rb0 = *(const float4*)(Bptr);
    rb1 = *(const float4*)(Bptr + (size_t)8 * N);
    {
        float av[8] = {ra0.x, ra0.y, ra0.z, ra0.w, ra1.x, ra1.y, ra1.z, ra1.w};
#pragma unroll
        for (int u = 0; u < 8; u++) As[a_col + u][a_row] = av[u];
        *(float4*)&Bs[b_row][b_col]     = rb0;
        *(float4*)&Bs[b_row + 8][b_col] = rb1;
    }

    const int ntiles = K >> 4;
    for (int kt = 0; kt < ntiles; kt++) {
        __syncthreads();
        if (kt + 1 < ntiles) {
            const float* Ap = Aptr + (kt + 1) * 16;
            ra0 = *(const float4*)(Ap);
            ra1 = *(const float4*)(Ap + 4);
            const float* Bp = Bptr + (size_t)(kt + 1) * 16 * N;
            rb0 = *(const float4*)(Bp);
            rb1 = *(const float4*)(Bp + (size_t)8 * N);
        }
#pragma unroll
        for (int k = 0; k < 16; k++) {
            float a[8], b[8];
            *(float4*)(a)     = *(const float4*)&As[k][tr];
            *(float4*)(a + 4) = *(const float4*)&As[k][tr + 4];
            *(float4*)(b)     = *(const float4*)&Bs[k][tc];
            *(float4*)(b + 4) = *(const float4*)&Bs[k][tc + 4];
#pragma unroll
            for (int i = 0; i < 8; i++)
#pragma unroll
                for (int j = 0; j < 8; j++)
                    acc[i][j] = fmaf(a[i], b[j], acc[i][j]);
        }
        __syncthreads();
        if (kt + 1 < ntiles) {
            float av[8] = {ra0.x, ra0.y, ra0.z, ra0.w, ra1.x, ra1.y, ra1.z, ra1.w};
#pragma unroll
            for (int u = 0; u < 8; u++) As[a_col + u][a_row] = av[u];
            *(float4*)&Bs[b_row][b_col]     = rb0;
            *(float4*)&Bs[b_row + 8][b_col] = rb1;
        }
    }

    // epilogue
#pragma unroll
    for (int i = 0; i < 8; i++) {
        const size_t row_off = (size_t)(brow + tr + i) * N + bcol + tc;
#pragma unroll
        for (int j = 0; j < 8; j++) {
            float v = acc[i][j] + bias[bcol + tc + j];
            if (mode == 1) v += R[row_off + j];
            else if (mode == 2) v = 0.5f * v * (1.f + erff(v * 0.70710678118654752f));
            C[row_off + j] = v;
        }
    }
}

// ---------------------------------------------------------------------------
// Flash attention: grid (32 q-tiles, 64 b*h), 256 threads.
// Q/K/V tiles 64x64 in dynamic smem with pad 65; online softmax.
// ---------------------------------------------------------------------------
#define APAD 65
#define ATTN_SMEM (4 * 64 * APAD * 4)

__global__ __launch_bounds__(256) void attn_kernel(
    const float* __restrict__ qkv, float* __restrict__ O)
{
    extern __shared__ float sm[];
    float* Qs = sm;
    float* Ks = Qs + 64 * APAD;
    float* Vs = Ks + 64 * APAD;
    float* Ps = Vs + 64 * APAD;

    const int qt = blockIdx.x;        // 0..31
    const int bh = blockIdx.y;        // 0..63
    const int b  = bh >> 4;
    const int h  = bh & 15;
    const int tid = threadIdx.x;
    const int ty = tid >> 4, tx = tid & 15;
    const int r0 = ty * 4, c0 = tx * 4;

    const size_t row_base = (size_t)b * S_;
    const int qoff = h * HD_;
    const int koff = H_ + h * HD_;
    const int voff = 2 * H_ + h * HD_;

    // load Q tile
    for (int idx = tid; idx < 64 * 64; idx += 256) {
        const int r = idx >> 6, d = idx & 63;
        Qs[r * APAD + d] = qkv[(row_base + qt * 64 + r) * QKV_N + qoff + d];
    }

    float m_i[4], l_i[4], o_acc[4][4];
#pragma unroll
    for (int i = 0; i < 4; i++) {
        m_i[i] = -1e30f; l_i[i] = 0.f;
#pragma unroll
        for (int j = 0; j < 4; j++) o_acc[i][j] = 0.f;
    }
    __syncthreads();

    const float scale = 0.125f;  // 1/sqrt(64)

    for (int kt = 0; kt < S_ / 64; kt++) {
        // load K,V tiles
        for (int idx = tid; idx < 64 * 64; idx += 256) {
            const int r = idx >> 6, d = idx & 63;
            const size_t base = (row_base + kt * 64 + r) * QKV_N;
            Ks[r * APAD + d] = qkv[base + koff + d];
            Vs[r * APAD + d] = qkv[base + voff + d];
        }
        __syncthreads();

        // S = Q @ K^T
        float s_acc[4][4];
#pragma unroll
        for (int i = 0; i < 4; i++)
#pragma unroll
            for (int j = 0; j < 4; j++) s_acc[i][j] = 0.f;

#pragma unroll 8
        for (int k = 0; k < 64; k++) {
            float a[4], bv[4];
#pragma unroll
            for (int i = 0; i < 4; i++) a[i]  = Qs[(r0 + i) * APAD + k];
#pragma unroll
            for (int j = 0; j < 4; j++) bv[j] = Ks[(c0 + j) * APAD + k];
#pragma unroll
            for (int i = 0; i < 4; i++)
#pragma unroll
                for (int j = 0; j < 4; j++)
                    s_acc[i][j] = fmaf(a[i], bv[j], s_acc[i][j]);
        }

        // online softmax per row
#pragma unroll
        for (int i = 0; i < 4; i++) {
            float mx = -1e30f;
#pragma unroll
            for (int j = 0; j < 4; j++) {
                s_acc[i][j] *= scale;
                mx = fmaxf(mx, s_acc[i][j]);
            }
#pragma unroll
            for (int off = 8; off > 0; off >>= 1)
                mx = fmaxf(mx, __shfl_xor_sync(0xffffffffu, mx, off));

            const float m_new = fmaxf(m_i[i], mx);
            const float corr  = __expf(m_i[i] - m_new);
            float rsum = 0.f;
#pragma unroll
            for (int j = 0; j < 4; j++) {
                s_acc[i][j] = __expf(s_acc[i][j] - m_new);
                rsum += s_acc[i][j];
            }
#pragma unroll
            for (int off = 8; off > 0; off >>= 1)
                rsum += __shfl_xor_sync(0xffffffffu, rsum, off);

            l_i[i] = l_i[i] * corr + rsum;
            m_i[i] = m_new;
#pragma unroll
            for (int j = 0; j < 4; j++) {
                o_acc[i][j] *= corr;
                Ps[(r0 + i) * APAD + c0 + j] = s_acc[i][j];
            }
        }
        __syncthreads();

        // O += P @ V
#pragma unroll 8
        for (int c = 0; c < 64; c++) {
            float a[4], bv[4];
#pragma unroll
            for (int i = 0; i < 4; i++) a[i]  = Ps[(r0 + i) * APAD + c];
#pragma unroll
            for (int j = 0; j < 4; j++) bv[j] = Vs[c * APAD + c0 + j];
#pragma unroll
            for (int i = 0; i < 4; i++)
#pragma unroll
                for (int j = 0; j < 4; j++)
                    o_acc[i][j] = fmaf(a[i], bv[j], o_acc[i][j]);
        }
        __syncthreads();
    }

    // write O[b, s, h*64+d]
#pragma unroll
    for (int i = 0; i < 4; i++) {
        const float inv_l = 1.f / l_i[i];
        const size_t orow = (row_base + qt * 64 + r0 + i) * H_ + h * HD_ + c0;
#pragma unroll
        for (int j = 0; j < 4; j++)
            O[orow + j] = o_acc[i][j] * inv_l;
    }
}

// ---------------------------------------------------------------------------
// Launch
// ---------------------------------------------------------------------------
extern "C" void kernel_launch(void* const* d_in, const int* in_sizes, int n_in,
                              void* d_out, int out_size)
{
    const float* x     = (const float*)d_in[0];
    const float* ln1_w = (const float*)d_in[1];
    const float* ln1_b = (const float*)d_in[2];
    const float* Wqkv  = (const float*)d_in[3];
    const float* bqkv  = (const float*)d_in[4];
    const float* Wo    = (const float*)d_in[5];
    const float* bo    = (const float*)d_in[6];
    const float* ln2_w = (const float*)d_in[7];
    const float* ln2_b = (const float*)d_in[8];
    const float* fc1_w = (const float*)d_in[9];
    const float* fc1_b = (const float*)d_in[10];
    const float* fc2_w = (const float*)d_in[11];
    const float* fc2_b = (const float*)d_in[12];
    float* out = (float*)d_out;

    float *h, *qkv, *o, *x2, *h2, *a;
    cudaGetSymbolAddress((void**)&h,   g_h);
    cudaGetSymbolAddress((void**)&qkv, g_qkv);
    cudaGetSymbolAddress((void**)&o,   g_o);
    cudaGetSymbolAddress((void**)&x2,  g_x2);
    cudaGetSymbolAddress((void**)&h2,  g_h2);
    cudaGetSymbolAddress((void**)&a,   g_a);

    cudaFuncSetAttribute(attn_kernel,
                         cudaFuncAttributeMaxDynamicSharedMemorySize, ATTN_SMEM);

    // 1) LN1
    ln_kernel<<<M_, 256>>>(x, ln1_w, ln1_b, h);
    // 2) QKV projection
    gemm_kernel<<<dim3(QKV_N / 128, M_ / 128), 256>>>(
        h, Wqkv, bqkv, nullptr, qkv, M_, QKV_N, H_, 0);
    // 3) attention
    attn_kernel<<<dim3(S_ / 64, B_ * NH_), 256, ATTN_SMEM>>>(qkv, o);
    // 4) Wo + residual
    gemm_kernel<<<dim3(H_ / 128, M_ / 128), 256>>>(
        o, Wo, bo, x, x2, M_, H_, H_, 1);
    // 5) LN2
    ln_kernel<<<M_, 256>>>(x2, ln2_w, ln2_b, h2);
    // 6) FC1 + GELU
    gemm_kernel<<<dim3(E_ / 128, M_ / 128), 256>>>(
        h2, fc1_w, fc1_b, nullptr, a, M_, E_, H_, 2);
    // 7) FC2 + residual -> out
    gemm_kernel<<<dim3(H_ / 128, M_ / 128), 256>>>(
        a, fc2_w, fc2_b, x2, out, M_, H_, E_, 1);
}

// round 3
// speedup vs baseline: 1.7332x; 1.7332x over previous
#include <cuda_runtime.h>
#include <cstdint>
#include <math.h>

// ---------------------------------------------------------------------------
// Problem constants
// ---------------------------------------------------------------------------
#define B_   4
#define S_   2048
#define H_   1024
#define NH_  16
#define HD_  64
#define E_   4096
#define M_   (B_ * S_)          // 8192 tokens
#define QKV_N (3 * H_)          // 3072

// ---------------------------------------------------------------------------
// Scratch (device globals — no allocation allowed)
// ---------------------------------------------------------------------------
__device__ float g_h  [M_ * H_];     // ln1 output
__device__ float g_qkv[M_ * QKV_N];  // qkv projection
__device__ float g_o  [M_ * H_];     // attention output (B,S,C)
__device__ float g_x2 [M_ * H_];     // x + attn@Wo + bo
__device__ float g_h2 [M_ * H_];     // ln2 output
__device__ float g_a  [M_ * E_];     // gelu(fc1)

// ---------------------------------------------------------------------------
// mma.sync tf32 helpers (sm_80+; runs on tensor pipe via HMMA)
// ---------------------------------------------------------------------------
__device__ __forceinline__ uint32_t f2tf32(float x) {
    uint32_t r;
    asm("cvt.rna.tf32.f32 %0, %1;" : "=r"(r) : "f"(x));
    return r;
}

__device__ __forceinline__ void mma_tf32(float* c, const uint32_t* a, const uint32_t* b) {
    asm volatile(
        "mma.sync.aligned.m16n8k8.row.col.f32.tf32.tf32.f32 "
        "{%0,%1,%2,%3}, {%4,%5,%6,%7}, {%8,%9}, {%0,%1,%2,%3};"
        : "+f"(c[0]), "+f"(c[1]), "+f"(c[2]), "+f"(c[3])
        : "r"(a[0]), "r"(a[1]), "r"(a[2]), "r"(a[3]), "r"(b[0]), "r"(b[1]));
}

// ---------------------------------------------------------------------------
// TF32 tensor-core GEMM: C[M,N] = A[M,K] @ B[K,N] + bias (+residual / gelu)
// mode 0: bias; mode 1: bias + residual R; mode 2: bias + exact GELU
// CTA 128x128x16, 128 threads, 4 warps (2x2), warp tile 64x64.
// Smem K-major [BK][BM+8] for both operands; double buffered.
// ---------------------------------------------------------------------------
#define BM 128
#define BN 128
#define BK 16
#define SSTR 136   // (128+8) words per k-row: conflict-free fragment LDS

__global__ __launch_bounds__(128) void gemm_mma(
    const float* __restrict__ A, const float* __restrict__ B,
    const float* __restrict__ bias, const float* __restrict__ R,
    float* __restrict__ C, int M, int N, int K, int mode)
{
    __shared__ uint32_t As[2][BK * SSTR];
    __shared__ uint32_t Bs[2][BK * SSTR];

    const int tid  = threadIdx.x;
    const int wid  = tid >> 5;
    const int lane = tid & 31;
    const int gID  = lane >> 2;
    const int tIG  = lane & 3;
    const int warp_m = wid & 1;        // 2 warps along M
    const int warp_n = wid >> 1;       // 2 warps along N
    const int brow = blockIdx.y * BM;
    const int bcol = blockIdx.x * BN;

    // --- global load assignments ---
    // A: thread owns row (brow+tid), 16 floats (4 float4 along K)
    const float* Ag = A + (size_t)(brow + tid) * K;
    // B: thread owns 4 k-rows {tid>>5 + 4p}, n = (tid&31)*4
    const int bk0 = tid >> 5;             // 0..3
    const int bn0 = (tid & 31) * 4;       // 0..124
    const float* Bg = B + (size_t)bk0 * N + bcol + bn0;

    float acc[4][8][4];
#pragma unroll
    for (int i = 0; i < 4; i++)
#pragma unroll
        for (int j = 0; j < 8; j++)
#pragma unroll
            for (int t = 0; t < 4; t++) acc[i][j][t] = 0.f;

    const int ntiles = K / BK;

    float4 ra[4], rb[4];
    // initial tile -> regs
#pragma unroll
    for (int p = 0; p < 4; p++) ra[p] = *(const float4*)(Ag + p * 4);
#pragma unroll
    for (int p = 0; p < 4; p++) rb[p] = *(const float4*)(Bg + (size_t)(4 * p) * N);
    // regs -> smem[0]
    {
        uint32_t* as = As[0];
        uint32_t* bs = Bs[0];
#pragma unroll
        for (int p = 0; p < 4; p++) {
            as[(p * 4 + 0) * SSTR + tid] = f2tf32(ra[p].x);
            as[(p * 4 + 1) * SSTR + tid] = f2tf32(ra[p].y);
            as[(p * 4 + 2) * SSTR + tid] = f2tf32(ra[p].z);
            as[(p * 4 + 3) * SSTR + tid] = f2tf32(ra[p].w);
            uint32_t* dst = &bs[(bk0 + 4 * p) * SSTR + bn0];
            dst[0] = f2tf32(rb[p].x); dst[1] = f2tf32(rb[p].y);
            dst[2] = f2tf32(rb[p].z); dst[3] = f2tf32(rb[p].w);
        }
    }
    __syncthreads();

    const int m_base = warp_m * 64;
    const int n_base = warp_n * 64;

    for (int kt = 0; kt < ntiles; kt++) {
        const int buf = kt & 1;
        if (kt + 1 < ntiles) {
            const float* Ap = Ag + (kt + 1) * BK;
#pragma unroll
            for (int p = 0; p < 4; p++) ra[p] = *(const float4*)(Ap + p * 4);
            const float* Bp = Bg + (size_t)((kt + 1) * BK) * N;
#pragma unroll
            for (int p = 0; p < 4; p++) rb[p] = *(const float4*)(Bp + (size_t)(4 * p) * N);
        }

        const uint32_t* as = As[buf];
        const uint32_t* bs = Bs[buf];
#pragma unroll
        for (int ks = 0; ks < 2; ks++) {
            const int k0 = ks * 8;
            uint32_t afr[4][4], bfr[8][2];
#pragma unroll
            for (int mt = 0; mt < 4; mt++) {
                const int m0 = m_base + mt * 16;
                afr[mt][0] = as[(k0 + tIG)     * SSTR + m0 + gID];
                afr[mt][1] = as[(k0 + tIG)     * SSTR + m0 + gID + 8];
                afr[mt][2] = as[(k0 + tIG + 4) * SSTR + m0 + gID];
                afr[mt][3] = as[(k0 + tIG + 4) * SSTR + m0 + gID + 8];
            }
#pragma unroll
            for (int nt = 0; nt < 8; nt++) {
                const int n0 = n_base + nt * 8;
                bfr[nt][0] = bs[(k0 + tIG)     * SSTR + n0 + gID];
                bfr[nt][1] = bs[(k0 + tIG + 4) * SSTR + n0 + gID];
            }
#pragma unroll
            for (int mt = 0; mt < 4; mt++)
#pragma unroll
                for (int nt = 0; nt < 8; nt++)
                    mma_tf32(acc[mt][nt], afr[mt], bfr[nt]);
        }

        if (kt + 1 < ntiles) {
            uint32_t* asn = As[buf ^ 1];
            uint32_t* bsn = Bs[buf ^ 1];
#pragma unroll
            for (int p = 0; p < 4; p++) {
                asn[(p * 4 + 0) * SSTR + tid] = f2tf32(ra[p].x);
                asn[(p * 4 + 1) * SSTR + tid] = f2tf32(ra[p].y);
                asn[(p * 4 + 2) * SSTR + tid] = f2tf32(ra[p].z);
                asn[(p * 4 + 3) * SSTR + tid] = f2tf32(ra[p].w);
                uint32_t* dst = &bsn[(bk0 + 4 * p) * SSTR + bn0];
                dst[0] = f2tf32(rb[p].x); dst[1] = f2tf32(rb[p].y);
                dst[2] = f2tf32(rb[p].z); dst[3] = f2tf32(rb[p].w);
            }
        }
        __syncthreads();
    }

    // --- epilogue: acc[mt][nt] c-regs -> C with bias (+R / gelu) ---
#pragma unroll
    for (int mt = 0; mt < 4; mt++) {
#pragma unroll
        for (int half = 0; half < 2; half++) {
            const int row = brow + m_base + mt * 16 + gID + half * 8;
            float* crow = C + (size_t)row * N;
            const float* rrow = (mode == 1) ? (R + (size_t)row * N) : nullptr;
#pragma unroll
            for (int nt = 0; nt < 8; nt++) {
                const int col = bcol + n_base + nt * 8 + tIG * 2;
                float v0 = acc[mt][nt][half * 2 + 0];
                float v1 = acc[mt][nt][half * 2 + 1];
                const float2 bb = *(const float2*)(bias + col);
                v0 += bb.x; v1 += bb.y;
                if (mode == 1) {
                    const float2 rr = *(const float2*)(rrow + col);
                    v0 += rr.x; v1 += rr.y;
                } else if (mode == 2) {
                    v0 = 0.5f * v0 * (1.f + erff(v0 * 0.70710678118654752f));
                    v1 = 0.5f * v1 * (1.f + erff(v1 * 0.70710678118654752f));
                }
                *(float2*)(crow + col) = make_float2(v0, v1);
            }
        }
    }
}

// ---------------------------------------------------------------------------
// LayerNorm: one block per row of 1024
// ---------------------------------------------------------------------------
__global__ __launch_bounds__(256) void ln_kernel(
    const float* __restrict__ x, const float* __restrict__ w,
    const float* __restrict__ b, float* __restrict__ out)
{
    const int row = blockIdx.x;
    const int tid = threadIdx.x;
    const float* xr = x + (size_t)row * H_;

    float v[4];
    float s = 0.f, s2 = 0.f;
#pragma unroll
    for (int i = 0; i < 4; i++) {
        v[i] = xr[tid + 256 * i];
        s += v[i];
        s2 += v[i] * v[i];
    }
#pragma unroll
    for (int off = 16; off > 0; off >>= 1) {
        s  += __shfl_xor_sync(0xffffffffu, s,  off);
        s2 += __shfl_xor_sync(0xffffffffu, s2, off);
    }
    __shared__ float red[8], red2[8];
    const int wid = tid >> 5, lane = tid & 31;
    if (lane == 0) { red[wid] = s; red2[wid] = s2; }
    __syncthreads();
    if (tid < 32) {
        float a = (tid < 8) ? red[tid]  : 0.f;
        float c = (tid < 8) ? red2[tid] : 0.f;
#pragma unroll
        for (int off = 4; off > 0; off >>= 1) {
            a += __shfl_xor_sync(0xffffffffu, a, off);
            c += __shfl_xor_sync(0xffffffffu, c, off);
        }
        if (tid == 0) { red[0] = a; red2[0] = c; }
    }
    __syncthreads();
    const float mu  = red[0] * (1.f / H_);
    const float var = red2[0] * (1.f / H_) - mu * mu;
    const float rstd = rsqrtf(var + 1e-5f);

    float* orow = out + (size_t)row * H_;
#pragma unroll
    for (int i = 0; i < 4; i++) {
        const int c = tid + 256 * i;
        orow[c] = (v[i] - mu) * rstd * w[c] + b[c];
    }
}

// ---------------------------------------------------------------------------
// Flash attention: grid (32 q-tiles, 64 b*h), 256 threads.
// ---------------------------------------------------------------------------
#define APAD 65
#define ATTN_SMEM (4 * 64 * APAD * 4)

__global__ __launch_bounds__(256) void attn_kernel(
    const float* __restrict__ qkv, float* __restrict__ O)
{
    extern __shared__ float sm[];
    float* Qs = sm;
    float* Ks = Qs + 64 * APAD;
    float* Vs = Ks + 64 * APAD;
    float* Ps = Vs + 64 * APAD;

    const int qt = blockIdx.x;
    const int bh = blockIdx.y;
    const int b  = bh >> 4;
    const int h  = bh & 15;
    const int tid = threadIdx.x;
    const int ty = tid >> 4, tx = tid & 15;
    const int r0 = ty * 4, c0 = tx * 4;

    const size_t row_base = (size_t)b * S_;
    const int qoff = h * HD_;
    const int koff = H_ + h * HD_;
    const int voff = 2 * H_ + h * HD_;

    for (int idx = tid; idx < 64 * 64; idx += 256) {
        const int r = idx >> 6, d = idx & 63;
        Qs[r * APAD + d] = qkv[(row_base + qt * 64 + r) * QKV_N + qoff + d];
    }

    float m_i[4], l_i[4], o_acc[4][4];
#pragma unroll
    for (int i = 0; i < 4; i++) {
        m_i[i] = -1e30f; l_i[i] = 0.f;
#pragma unroll
        for (int j = 0; j < 4; j++) o_acc[i][j] = 0.f;
    }
    __syncthreads();

    const float scale = 0.125f;

    for (int kt = 0; kt < S_ / 64; kt++) {
        for (int idx = tid; idx < 64 * 64; idx += 256) {
            const int r = idx >> 6, d = idx & 63;
            const size_t base = (row_base + kt * 64 + r) * QKV_N;
            Ks[r * APAD + d] = qkv[base + koff + d];
            Vs[r * APAD + d] = qkv[base + voff + d];
        }
        __syncthreads();

        float s_acc[4][4];
#pragma unroll
        for (int i = 0; i < 4; i++)
#pragma unroll
            for (int j = 0; j < 4; j++) s_acc[i][j] = 0.f;

#pragma unroll 8
        for (int k = 0; k < 64; k++) {
            float a[4], bv[4];
#pragma unroll
            for (int i = 0; i < 4; i++) a[i]  = Qs[(r0 + i) * APAD + k];
#pragma unroll
            for (int j = 0; j < 4; j++) bv[j] = Ks[(c0 + j) * APAD + k];
#pragma unroll
            for (int i = 0; i < 4; i++)
#pragma unroll
                for (int j = 0; j < 4; j++)
                    s_acc[i][j] = fmaf(a[i], bv[j], s_acc[i][j]);
        }

#pragma unroll
        for (int i = 0; i < 4; i++) {
            float mx = -1e30f;
#pragma unroll
            for (int j = 0; j < 4; j++) {
                s_acc[i][j] *= scale;
                mx = fmaxf(mx, s_acc[i][j]);
            }
#pragma unroll
            for (int off = 8; off > 0; off >>= 1)
                mx = fmaxf(mx, __shfl_xor_sync(0xffffffffu, mx, off));

            const float m_new = fmaxf(m_i[i], mx);
            const float corr  = __expf(m_i[i] - m_new);
            float rsum = 0.f;
#pragma unroll
            for (int j = 0; j < 4; j++) {
                s_acc[i][j] = __expf(s_acc[i][j] - m_new);
                rsum += s_acc[i][j];
            }
#pragma unroll
            for (int off = 8; off > 0; off >>= 1)
                rsum += __shfl_xor_sync(0xffffffffu, rsum, off);

            l_i[i] = l_i[i] * corr + rsum;
            m_i[i] = m_new;
#pragma unroll
            for (int j = 0; j < 4; j++) {
                o_acc[i][j] *= corr;
                Ps[(r0 + i) * APAD + c0 + j] = s_acc[i][j];
            }
        }
        __syncthreads();

#pragma unroll 8
        for (int c = 0; c < 64; c++) {
            float a[4], bv[4];
#pragma unroll
            for (int i = 0; i < 4; i++) a[i]  = Ps[(r0 + i) * APAD + c];
#pragma unroll
            for (int j = 0; j < 4; j++) bv[j] = Vs[c * APAD + c0 + j];
#pragma unroll
            for (int i = 0; i < 4; i++)
#pragma unroll
                for (int j = 0; j < 4; j++)
                    o_acc[i][j] = fmaf(a[i], bv[j], o_acc[i][j]);
        }
        __syncthreads();
    }

#pragma unroll
    for (int i = 0; i < 4; i++) {
        const float inv_l = 1.f / l_i[i];
        const size_t orow = (row_base + qt * 64 + r0 + i) * H_ + h * HD_ + c0;
#pragma unroll
        for (int j = 0; j < 4; j++)
            O[orow + j] = o_acc[i][j] * inv_l;
    }
}

// ---------------------------------------------------------------------------
// Launch
// ---------------------------------------------------------------------------
extern "C" void kernel_launch(void* const* d_in, const int* in_sizes, int n_in,
                              void* d_out, int out_size)
{
    const float* x     = (const float*)d_in[0];
    const float* ln1_w = (const float*)d_in[1];
    const float* ln1_b = (const float*)d_in[2];
    const float* Wqkv  = (const float*)d_in[3];
    const float* bqkv  = (const float*)d_in[4];
    const float* Wo    = (const float*)d_in[5];
    const float* bo    = (const float*)d_in[6];
    const float* ln2_w = (const float*)d_in[7];
    const float* ln2_b = (const float*)d_in[8];
    const float* fc1_w = (const float*)d_in[9];
    const float* fc1_b = (const float*)d_in[10];
    const float* fc2_w = (const float*)d_in[11];
    const float* fc2_b = (const float*)d_in[12];
    float* out = (float*)d_out;

    float *h, *qkv, *o, *x2, *h2, *a;
    cudaGetSymbolAddress((void**)&h,   g_h);
    cudaGetSymbolAddress((void**)&qkv, g_qkv);
    cudaGetSymbolAddress((void**)&o,   g_o);
    cudaGetSymbolAddress((void**)&x2,  g_x2);
    cudaGetSymbolAddress((void**)&h2,  g_h2);
    cudaGetSymbolAddress((void**)&a,   g_a);

    cudaFuncSetAttribute(attn_kernel,
                         cudaFuncAttributeMaxDynamicSharedMemorySize, ATTN_SMEM);

    // 1) LN1
    ln_kernel<<<M_, 256>>>(x, ln1_w, ln1_b, h);
    // 2) QKV projection (tf32 mma.sync)
    gemm_mma<<<dim3(QKV_N / BN, M_ / BM), 128>>>(
        h, Wqkv, bqkv, nullptr, qkv, M_, QKV_N, H_, 0);
    // 3) attention
    attn_kernel<<<dim3(S_ / 64, B_ * NH_), 256, ATTN_SMEM>>>(qkv, o);
    // 4) Wo + residual
    gemm_mma<<<dim3(H_ / BN, M_ / BM), 128>>>(
        o, Wo, bo, x, x2, M_, H_, H_, 1);
    // 5) LN2
    ln_kernel<<<M_, 256>>>(x2, ln2_w, ln2_b, h2);
    // 6) FC1 + GELU
    gemm_mma<<<dim3(E_ / BN, M_ / BM), 128>>>(
        h2, fc1_w, fc1_b, nullptr, a, M_, E_, H_, 2);
    // 7) FC2 + residual -> out
    gemm_mma<<<dim3(H_ / BN, M_ / BM), 128>>>(
        a, fc2_w, fc2_b, x2, out, M_, H_, E_, 1);
}